// round 15
// baseline (speedup 1.0000x reference)
#include <cuda_runtime.h>
#include <cstdint>

// Pair_83811991814342
// in:  (1, 1024, 260) fp32; only first 512 rows used
// out: (1, 512*512, 522) fp32 : [x[i](260) | x[j](260) | r1 | r2]
// Persistent-CTA TMA bulk-store pipeline: 888 blocks, dynamic tile stealing,
// continuous 4-deep bulk-group ring across tiles (never drains mid-kernel).

#define NROWS 512
#define DIM   260
#define ROWB  2088                  // output bytes per row
#define RPG   4                     // rows per group
#define GRPB  (RPG * ROWB)          // 8352 B per group
#define NBUF  4
#define NT    288
#define NTILE 4096                  // 64 x 64 tiles of 8x8 pairs
#define GRID  888                   // 148 SMs * 6 CTAs

__device__ unsigned g_ctr;

__global__ void reset_kernel() { g_ctr = GRID; }

__device__ __forceinline__ uint32_t smem_u32(const void* p) {
    uint32_t a;
    asm("{ .reg .u64 t; cvta.to.shared.u64 t, %1; cvt.u32.u64 %0, t; }"
        : "=r"(a) : "l"(p));
    return a;
}

__global__ __launch_bounds__(NT, 6)
void pair_kernel(const float* __restrict__ in, float* __restrict__ out) {
    __shared__ __align__(16) char s_buf[NBUF][GRPB];
    __shared__ float2 s_r[64];                      // (r1, r2) per (il, jl)
    __shared__ unsigned s_tile;

    const int t = threadIdx.x;
    const int c = t;                                // float2 column [0,261)
    const bool isI = (c < 130);
    const bool isJ = (c >= 130) && (c < 260);

    unsigned tile = blockIdx.x;                     // first tile: static
    unsigned gg = 0;                                // bulk-groups committed

    while (tile < NTILE) {
        const int bi = (int)(tile >> 6) * 8;
        const int bj = (int)(tile & 63) * 8;

        // ---- Grab next tile (t0), preload v, compute r-table ----
        if (t == 0) s_tile = atomicAdd(&g_ctr, 1u);

        float2 v[8];
        if (c < 260) {
            const float2* base = reinterpret_cast<const float2*>(in)
                + (isI ? ((size_t)bi * (DIM / 2) + c)
                       : ((size_t)bj * (DIM / 2) + (c - 130)));
            #pragma unroll
            for (int r = 0; r < 8; r++)
                v[r] = __ldg(&base[(size_t)r * (DIM / 2)]);
        }
        if (t < 64) {
            int il = t >> 3, jl = t & 7;
            const float4 a = __ldg(reinterpret_cast<const float4*>(
                in + (bi + il) * DIM + (DIM - 4)));
            const float4 b = __ldg(reinterpret_cast<const float4*>(
                in + (bj + jl) * DIM + (DIM - 4)));
            float w = fmaxf(0.0f, fminf(a.z, b.z) - fmaxf(a.x, b.x));
            float h = fmaxf(0.0f, fminf(a.w, b.w) - fmaxf(a.y, b.y));
            float inter = w * h;
            s_r[t] = make_float2(inter / ((a.z - a.x) * (a.w - a.y)),
                                 inter / ((b.z - b.x) * (b.w - b.y)));
        }
        __syncthreads();                            // s_r + s_tile published
        const unsigned next_tile = s_tile;

        // ---- 16 groups: g = (il = g/2, jl in [4*(g&1), +4)) ----
        #pragma unroll
        for (int g = 0; g < 16; g++) {
            const int il = g >> 1;
            const int hb = g & 1;
            if (gg >= NBUF) {                       // recycle ring slot
                if (t == 0)
                    asm volatile("cp.async.bulk.wait_group.read 3;" ::: "memory");
                __syncthreads();
            }
            char* const buf = s_buf[gg & (NBUF - 1)];

            if (c < 261) {
                char* p = buf + c * 8;
                #pragma unroll
                for (int k = 0; k < 4; k++) {
                    const int jl4 = 4 * hb + k;
                    float2 val;
                    if (isI)      val = v[il];      // compile-time reg index
                    else if (isJ) val = v[jl4];     // compile-time reg index
                    else          val = s_r[(il << 3) | jl4];
                    *reinterpret_cast<float2*>(p + k * ROWB) = val;
                }
            }
            __syncthreads();

            if (t == 0) {
                asm volatile("fence.proxy.async.shared::cta;" ::: "memory");
                const float* gdst = out
                    + ((size_t)(bi + il) * NROWS + bj + 4 * hb) * 522;
                asm volatile(
                    "cp.async.bulk.global.shared::cta.bulk_group [%0], [%1], %2;"
                    :: "l"(gdst), "r"(smem_u32(buf)), "r"((uint32_t)GRPB)
                    : "memory");
                asm volatile("cp.async.bulk.commit_group;" ::: "memory");
            }
            gg++;
        }

        tile = next_tile;
    }

    // Drain all pending bulk stores before exit
    if (t == 0)
        asm volatile("cp.async.bulk.wait_group 0;" ::: "memory");
}

extern "C" void kernel_launch(void* const* d_in, const int* in_sizes, int n_in,
                              void* d_out, int out_size) {
    const float* in = (const float*)d_in[0];
    float* out = (float*)d_out;
    reset_kernel<<<1, 1>>>();
    pair_kernel<<<GRID, NT>>>(in, out);
}

// round 16
// speedup vs baseline: 1.1217x; 1.1217x over previous
#include <cuda_runtime.h>
#include <cstdint>

// Pair_83811991814342
// in:  (1, 1024, 260) fp32; only first 512 rows used
// out: (1, 512*512, 522) fp32 : [x[i](260) | x[j](260) | r1 | r2]
// TMA bulk-store pipeline: 8 staging buffers of 2 output rows (4176 B),
// up to 7 bulk-groups in flight; input loads hoisted to registers.

#define NROWS 512
#define DIM   260
#define ROWB  2088                  // output bytes per row
#define RPG   2                     // rows per group
#define GRPB  (RPG * ROWB)          // 4176 B per group (mult 16; base 16-aligned)
#define NBUF  8
#define NT    288

__device__ __forceinline__ uint32_t smem_u32(const void* p) {
    uint32_t a;
    asm("{ .reg .u64 t; cvta.to.shared.u64 t, %1; cvt.u32.u64 %0, t; }"
        : "=r"(a) : "l"(p));
    return a;
}

__global__ __launch_bounds__(NT, 6)
void pair_kernel(const float* __restrict__ in, float* __restrict__ out) {
    __shared__ __align__(16) char s_buf[NBUF][GRPB];
    __shared__ float2 s_r[64];                      // (r1, r2) per (il, jl)

    const int bi = blockIdx.y * 8;
    const int bj = blockIdx.x * 8;
    const int t  = threadIdx.x;

    // ---- Threads 0..63: (r1, r2) table ----
    if (t < 64) {
        int il = t >> 3, jl = t & 7;
        const float4 a = __ldg(reinterpret_cast<const float4*>(
            in + (bi + il) * DIM + (DIM - 4)));
        const float4 b = __ldg(reinterpret_cast<const float4*>(
            in + (bj + jl) * DIM + (DIM - 4)));
        float w = fmaxf(0.0f, fminf(a.z, b.z) - fmaxf(a.x, b.x));
        float h = fmaxf(0.0f, fminf(a.w, b.w) - fmaxf(a.y, b.y));
        float inter = w * h;
        s_r[t] = make_float2(inter / ((a.z - a.x) * (a.w - a.y)),
                             inter / ((b.z - b.x) * (b.w - b.y)));
    }
    __syncthreads();

    const int c = t;                                // float2 column [0,261)
    const bool isI = (c < 130);
    const bool isJ = (c >= 130) && (c < 260);

    // ---- Hoisted preload: thread's 8 values (i-rows or j-rows) in registers ----
    float2 v[8];
    if (c < 260) {
        const float2* base = reinterpret_cast<const float2*>(in)
            + (isI ? ((size_t)bi * (DIM / 2) + c)
                   : ((size_t)bj * (DIM / 2) + (c - 130)));
        #pragma unroll
        for (int r = 0; r < 8; r++)
            v[r] = __ldg(&base[(size_t)r * (DIM / 2)]);
    }

    // 32 groups, fully unrolled: group g = (il = g/4, jl in [2*(g&3), +2))
    #pragma unroll
    for (int g = 0; g < 32; g++) {
        const int il = g >> 2;
        const int qb = g & 3;                       // jl quarter
        if (g >= NBUF) {
            if (t == 0)
                asm volatile("cp.async.bulk.wait_group.read 6;" ::: "memory");
            __syncthreads();
        }
        char* const buf = s_buf[g & (NBUF - 1)];

        if (c < 261) {
            char* p = buf + c * 8;
            #pragma unroll
            for (int k = 0; k < 2; k++) {
                const int jl2 = 2 * qb + k;
                float2 val;
                if (isI)      val = v[il];          // compile-time reg index
                else if (isJ) val = v[jl2];         // compile-time reg index
                else          val = s_r[(il << 3) | jl2];
                *reinterpret_cast<float2*>(p + k * ROWB) = val;
            }
        }
        __syncthreads();

        // ---- One bulk store: 4176 B smem -> gmem (2 contiguous rows) ----
        if (t == 0) {
            asm volatile("fence.proxy.async.shared::cta;" ::: "memory");
            const float* gdst = out
                + ((size_t)(bi + il) * NROWS + bj + 2 * qb) * 522;
            asm volatile(
                "cp.async.bulk.global.shared::cta.bulk_group [%0], [%1], %2;"
                :: "l"(gdst), "r"(smem_u32(buf)), "r"((uint32_t)GRPB)
                : "memory");
            asm volatile("cp.async.bulk.commit_group;" ::: "memory");
        }
    }

    // Drain all pending bulk stores before exit
    if (t == 0)
        asm volatile("cp.async.bulk.wait_group 0;" ::: "memory");
}

extern "C" void kernel_launch(void* const* d_in, const int* in_sizes, int n_in,
                              void* d_out, int out_size) {
    const float* in = (const float*)d_in[0];
    float* out = (float*)d_out;
    dim3 grid(NROWS / 8, NROWS / 8);  // 64 x 64 blocks
    pair_kernel<<<grid, NT>>>(in, out);
}